// round 5
// baseline (speedup 1.0000x reference)
#include <cuda_runtime.h>
#include <cuda_bf16.h>
#include <math.h>

#define N_NODES 50000
#define N_EDGES 800000
#define DIM_IN  128
#define DIM_H   64
#define DIM_OUT 16

// Scratch (allocation-free: __device__ globals)
__device__ float g_h0[N_NODES * DIM_H];    // x @ W1
__device__ float g_h1[N_NODES * DIM_H];    // spmm1 result (width 64)
__device__ float g_u[N_NODES * DIM_OUT];   // tanh(h1) @ (W2@W3)
__device__ float g_v[N_NODES * DIM_OUT];   // spmm2 result (width 16)

// CSR build scratch
__device__ int   g_hist[N_NODES];
__device__ int   g_row_ptr[N_NODES + 1];
__device__ int   g_cursor[N_NODES];
__device__ int   g_srt_src[N_EDGES];
__device__ float g_srt_val[N_EDGES];

__device__ __forceinline__ float tanh_fast(float x) {
    float y;
    asm("tanh.approx.f32 %0, %1;" : "=f"(y) : "f"(x));
    return y;
}

// ---- packed f32x2 helpers ----
__device__ __forceinline__ unsigned long long pack2(float a, float b) {
    unsigned long long r;
    asm("mov.b64 %0, {%1, %2};" : "=l"(r) : "f"(a), "f"(b));
    return r;
}
__device__ __forceinline__ void fma2(unsigned long long& d,
                                     unsigned long long a,
                                     unsigned long long b) {
    asm("fma.rn.f32x2 %0, %1, %2, %0;" : "+l"(d) : "l"(a), "l"(b));
}
__device__ __forceinline__ float2 unpack2(unsigned long long v) {
    float2 f;
    asm("mov.b64 {%0, %1}, %2;" : "=f"(f.x), "=f"(f.y) : "l"(v));
    return f;
}

// ================= CSR build: counting sort by dst =================

__global__ void hist_kernel(const int* __restrict__ dst) {
    int t = blockIdx.x * blockDim.x + threadIdx.x;
    if (t >= N_EDGES / 4) return;
    int4 d = ((const int4*)dst)[t];
    atomicAdd(&g_hist[d.x], 1);
    atomicAdd(&g_hist[d.y], 1);
    atomicAdd(&g_hist[d.z], 1);
    atomicAdd(&g_hist[d.w], 1);
}

// Single-block exclusive scan of g_hist -> g_row_ptr / g_cursor.
__global__ __launch_bounds__(1024) void scan_all_kernel() {
    __shared__ int warp_sums[32];
    __shared__ int carry;
    int tid = threadIdx.x;
    int lane = tid & 31, wid = tid >> 5;
    if (tid == 0) carry = 0;
    __syncthreads();

    for (int base = 0; base < N_NODES; base += 1024) {
        int gid = base + tid;
        int v = (gid < N_NODES) ? g_hist[gid] : 0;
        int incl = v;
#pragma unroll
        for (int o = 1; o < 32; o <<= 1) {
            int n = __shfl_up_sync(0xffffffffu, incl, o);
            if (lane >= o) incl += n;
        }
        if (lane == 31) warp_sums[wid] = incl;
        __syncthreads();
        if (wid == 0) {
            int s = warp_sums[lane];
#pragma unroll
            for (int o = 1; o < 32; o <<= 1) {
                int n = __shfl_up_sync(0xffffffffu, s, o);
                if (lane >= o) s += n;
            }
            warp_sums[lane] = s;
        }
        __syncthreads();
        int warp_off = (wid == 0) ? 0 : warp_sums[wid - 1];
        int excl = carry + warp_off + incl - v;
        if (gid < N_NODES) {
            g_row_ptr[gid] = excl;
            g_cursor[gid] = excl;
        }
        __syncthreads();          // everyone has read carry/warp_sums
        if (tid == 0) carry += warp_sums[31];
        __syncthreads();
    }
    if (tid == 0) g_row_ptr[N_NODES] = carry;
}

__global__ void scatter_kernel(const int* __restrict__ src,
                               const int* __restrict__ dst,
                               const float* __restrict__ vals) {
    int t = blockIdx.x * blockDim.x + threadIdx.x;
    if (t >= N_EDGES / 4) return;
    int4 s = ((const int4*)src)[t];
    int4 d = ((const int4*)dst)[t];
    float4 v = ((const float4*)vals)[t];
    int p;
    p = atomicAdd(&g_cursor[d.x], 1); g_srt_src[p] = s.x; g_srt_val[p] = v.x;
    p = atomicAdd(&g_cursor[d.y], 1); g_srt_src[p] = s.y; g_srt_val[p] = v.y;
    p = atomicAdd(&g_cursor[d.z], 1); g_srt_src[p] = s.z; g_srt_val[p] = v.z;
    p = atomicAdd(&g_cursor[d.w], 1); g_srt_src[p] = s.w; g_srt_val[p] = v.w;
}

// ================= dense kernels =================

// GEMM1: h0 = x @ W1  (50000x128 @ 128x64), 64-row tile, f32x2
#define G1_ROWS 64
__global__ __launch_bounds__(256) void gemm1_kernel(const float* __restrict__ x,
                                                    const float* __restrict__ W1) {
    extern __shared__ float smem[];
    float4* sW = (float4*)smem;                       // [128][16] float4
    float4* sx = (float4*)(smem + DIM_IN * DIM_H);    // [64][32] float4
    int tid = threadIdx.x;
    int row0 = blockIdx.x * G1_ROWS;

    const float4* W4 = (const float4*)W1;
    for (int i = tid; i < DIM_IN * 16; i += 256) sW[i] = W4[i];
    const float4* x4 = (const float4*)x;
    for (int i = tid; i < G1_ROWS * 32; i += 256) {
        int r = i >> 5, c = i & 31;
        sx[i] = (row0 + r < N_NODES) ? x4[(size_t)(row0 + r) * 32 + c]
                                     : make_float4(0.f, 0.f, 0.f, 0.f);
    }
    __syncthreads();

    int tx = tid & 15;
    int ty = tid >> 4;
    unsigned long long acc[4][2];
#pragma unroll
    for (int i = 0; i < 4; i++) { acc[i][0] = 0ull; acc[i][1] = 0ull; }

    for (int k4 = 0; k4 < DIM_IN / 4; k4++) {
        float4 w0 = sW[(4 * k4 + 0) * 16 + tx];
        float4 w1 = sW[(4 * k4 + 1) * 16 + tx];
        float4 w2 = sW[(4 * k4 + 2) * 16 + tx];
        float4 w3 = sW[(4 * k4 + 3) * 16 + tx];
        unsigned long long w0a = pack2(w0.x, w0.y), w0b = pack2(w0.z, w0.w);
        unsigned long long w1a = pack2(w1.x, w1.y), w1b = pack2(w1.z, w1.w);
        unsigned long long w2a = pack2(w2.x, w2.y), w2b = pack2(w2.z, w2.w);
        unsigned long long w3a = pack2(w3.x, w3.y), w3b = pack2(w3.z, w3.w);
#pragma unroll
        for (int i = 0; i < 4; i++) {
            float4 a = sx[(4 * ty + i) * 32 + k4];
            unsigned long long a0 = pack2(a.x, a.x);
            unsigned long long a1 = pack2(a.y, a.y);
            unsigned long long a2 = pack2(a.z, a.z);
            unsigned long long a3 = pack2(a.w, a.w);
            fma2(acc[i][0], a0, w0a); fma2(acc[i][1], a0, w0b);
            fma2(acc[i][0], a1, w1a); fma2(acc[i][1], a1, w1b);
            fma2(acc[i][0], a2, w2a); fma2(acc[i][1], a2, w2b);
            fma2(acc[i][0], a3, w3a); fma2(acc[i][1], a3, w3b);
        }
    }
#pragma unroll
    for (int i = 0; i < 4; i++) {
        int row = row0 + 4 * ty + i;
        if (row < N_NODES) {
            float2 lo = unpack2(acc[i][0]), hi = unpack2(acc[i][1]);
            ((float4*)(g_h0 + (size_t)row * DIM_H))[tx] =
                make_float4(lo.x, lo.y, hi.x, hi.y);
        }
    }
}

// SPMM width 64, CSR: 16 threads per dst node, 4-edge unroll for MLP
__global__ __launch_bounds__(256) void spmm64_csr_kernel(const float* __restrict__ h,
                                                         float* __restrict__ out) {
    int t = blockIdx.x * blockDim.x + threadIdx.x;
    int node = t >> 4, c = t & 15;
    if (node >= N_NODES) return;
    int i = g_row_ptr[node], end = g_row_ptr[node + 1];
    float4 acc = make_float4(0.f, 0.f, 0.f, 0.f);
    for (; i + 4 <= end; i += 4) {
        int s0 = g_srt_src[i], s1 = g_srt_src[i + 1];
        int s2 = g_srt_src[i + 2], s3 = g_srt_src[i + 3];
        float v0 = g_srt_val[i], v1 = g_srt_val[i + 1];
        float v2 = g_srt_val[i + 2], v3 = g_srt_val[i + 3];
        float4 a0 = ((const float4*)(h + (size_t)s0 * DIM_H))[c];
        float4 a1 = ((const float4*)(h + (size_t)s1 * DIM_H))[c];
        float4 a2 = ((const float4*)(h + (size_t)s2 * DIM_H))[c];
        float4 a3 = ((const float4*)(h + (size_t)s3 * DIM_H))[c];
        acc.x += a0.x * v0; acc.y += a0.y * v0; acc.z += a0.z * v0; acc.w += a0.w * v0;
        acc.x += a1.x * v1; acc.y += a1.y * v1; acc.z += a1.z * v1; acc.w += a1.w * v1;
        acc.x += a2.x * v2; acc.y += a2.y * v2; acc.z += a2.z * v2; acc.w += a2.w * v2;
        acc.x += a3.x * v3; acc.y += a3.y * v3; acc.z += a3.z * v3; acc.w += a3.w * v3;
    }
    for (; i < end; i++) {
        int s0 = g_srt_src[i];
        float v0 = g_srt_val[i];
        float4 a0 = ((const float4*)(h + (size_t)s0 * DIM_H))[c];
        acc.x += a0.x * v0; acc.y += a0.y * v0; acc.z += a0.z * v0; acc.w += a0.w * v0;
    }
    ((float4*)(out + (size_t)node * DIM_H))[c] = acc;
}

// u = tanh(h1) @ (W2@W3): W23 computed in-block (tiny), padded smem, f32x2
__global__ __launch_bounds__(256) void gemm2_tanh_kernel(const float* __restrict__ W2,
                                                         const float* __restrict__ W3) {
    __shared__ float sW2[DIM_H * DIM_H];   // 16 KB
    __shared__ float sW3[DIM_H * DIM_OUT]; // 4 KB
    __shared__ float4 sW[DIM_H * 4];       // W23 as [64][4] float4
    __shared__ float sh[64 * 65];          // 16.25 KB
    int tid = threadIdx.x;
    int row0 = blockIdx.x * 64;

    for (int i = tid; i < DIM_H * DIM_H / 4; i += 256)
        ((float4*)sW2)[i] = ((const float4*)W2)[i];
    for (int i = tid; i < DIM_H * DIM_OUT / 4; i += 256)
        ((float4*)sW3)[i] = ((const float4*)W3)[i];
    for (int i = tid; i < 64 * 16; i += 256) {
        int r = i >> 4, k4 = i & 15;
        float4 a = (row0 + r < N_NODES)
            ? ((const float4*)(g_h1 + (size_t)(row0 + r) * DIM_H))[k4]
            : make_float4(0.f, 0.f, 0.f, 0.f);
        float* p = sh + r * 65 + 4 * k4;
        p[0] = tanh_fast(a.x); p[1] = tanh_fast(a.y);
        p[2] = tanh_fast(a.z); p[3] = tanh_fast(a.w);
    }
    __syncthreads();

    // W23 = W2 @ W3: 256 threads, one float4 each (row i, col4 j)
    {
        int i = tid >> 2, j = tid & 3;
        float4 acc = make_float4(0.f, 0.f, 0.f, 0.f);
#pragma unroll 8
        for (int k = 0; k < DIM_H; k++) {
            float a = sW2[i * DIM_H + k];
            float4 w = ((const float4*)sW3)[k * 4 + j];
            acc.x += a * w.x; acc.y += a * w.y;
            acc.z += a * w.z; acc.w += a * w.w;
        }
        sW[i * 4 + j] = acc;
    }
    __syncthreads();

    int r = tid >> 2;
    int c4 = tid & 3;
    unsigned long long acc0 = 0ull, acc1 = 0ull;
#pragma unroll 8
    for (int k = 0; k < DIM_H; k++) {
        float a = sh[r * 65 + k];
        unsigned long long aa = pack2(a, a);
        float4 w = sW[k * 4 + c4];
        fma2(acc0, aa, pack2(w.x, w.y));
        fma2(acc1, aa, pack2(w.z, w.w));
    }
    if (row0 + r < N_NODES) {
        float2 lo = unpack2(acc0), hi = unpack2(acc1);
        ((float4*)(g_u + (size_t)(row0 + r) * DIM_OUT))[c4] =
            make_float4(lo.x, lo.y, hi.x, hi.y);
    }
}

// SPMM width 16, CSR: 4 threads per dst node
__global__ __launch_bounds__(256) void spmm16_csr_kernel(const float* __restrict__ h,
                                                         float* __restrict__ out) {
    int t = blockIdx.x * blockDim.x + threadIdx.x;
    int node = t >> 2, c = t & 3;
    if (node >= N_NODES) return;
    int i = g_row_ptr[node], end = g_row_ptr[node + 1];
    float4 acc = make_float4(0.f, 0.f, 0.f, 0.f);
    for (; i + 2 <= end; i += 2) {
        int s0 = g_srt_src[i], s1 = g_srt_src[i + 1];
        float v0 = g_srt_val[i], v1 = g_srt_val[i + 1];
        float4 a0 = ((const float4*)(h + (size_t)s0 * DIM_OUT))[c];
        float4 a1 = ((const float4*)(h + (size_t)s1 * DIM_OUT))[c];
        acc.x += a0.x * v0; acc.y += a0.y * v0; acc.z += a0.z * v0; acc.w += a0.w * v0;
        acc.x += a1.x * v1; acc.y += a1.y * v1; acc.z += a1.z * v1; acc.w += a1.w * v1;
    }
    if (i < end) {
        int s0 = g_srt_src[i];
        float v0 = g_srt_val[i];
        float4 a0 = ((const float4*)(h + (size_t)s0 * DIM_OUT))[c];
        acc.x += a0.x * v0; acc.y += a0.y * v0; acc.z += a0.z * v0; acc.w += a0.w * v0;
    }
    ((float4*)(out + (size_t)node * DIM_OUT))[c] = acc;
}

// SPMM width 16 + fused softmax: 4 threads per node, width-4 shfl reduce.
__global__ __launch_bounds__(256) void spmm16_softmax_kernel(const float* __restrict__ h,
                                                             float* __restrict__ out) {
    int t = blockIdx.x * blockDim.x + threadIdx.x;
    int node = t >> 2, c = t & 3;
    if (node >= N_NODES) return;
    int i = g_row_ptr[node], end = g_row_ptr[node + 1];
    float4 acc = make_float4(0.f, 0.f, 0.f, 0.f);
    for (; i + 2 <= end; i += 2) {
        int s0 = g_srt_src[i], s1 = g_srt_src[i + 1];
        float v0 = g_srt_val[i], v1 = g_srt_val[i + 1];
        float4 a0 = ((const float4*)(h + (size_t)s0 * DIM_OUT))[c];
        float4 a1 = ((const float4*)(h + (size_t)s1 * DIM_OUT))[c];
        acc.x += a0.x * v0; acc.y += a0.y * v0; acc.z += a0.z * v0; acc.w += a0.w * v0;
        acc.x += a1.x * v1; acc.y += a1.y * v1; acc.z += a1.z * v1; acc.w += a1.w * v1;
    }
    if (i < end) {
        int s0 = g_srt_src[i];
        float v0 = g_srt_val[i];
        float4 a0 = ((const float4*)(h + (size_t)s0 * DIM_OUT))[c];
        acc.x += a0.x * v0; acc.y += a0.y * v0; acc.z += a0.z * v0; acc.w += a0.w * v0;
    }
    // softmax across 16 values held by 4 consecutive lanes (4 each)
    float m = fmaxf(fmaxf(acc.x, acc.y), fmaxf(acc.z, acc.w));
    m = fmaxf(m, __shfl_xor_sync(0xffffffffu, m, 1));
    m = fmaxf(m, __shfl_xor_sync(0xffffffffu, m, 2));
    float4 e;
    e.x = __expf(acc.x - m); e.y = __expf(acc.y - m);
    e.z = __expf(acc.z - m); e.w = __expf(acc.w - m);
    float s = e.x + e.y + e.z + e.w;
    s += __shfl_xor_sync(0xffffffffu, s, 1);
    s += __shfl_xor_sync(0xffffffffu, s, 2);
    float inv = __frcp_rn(s);
    ((float4*)(out + (size_t)node * DIM_OUT))[c] =
        make_float4(e.x * inv, e.y * inv, e.z * inv, e.w * inv);
}

extern "C" void kernel_launch(void* const* d_in, const int* in_sizes, int n_in,
                              void* d_out, int out_size) {
    const float* x         = (const float*)d_in[0];
    const int*   edge_src  = (const int*)d_in[1];
    const int*   edge_dst  = (const int*)d_in[2];
    const float* edge_vals = (const float*)d_in[3];
    const float* W1        = (const float*)d_in[4];
    const float* W2        = (const float*)d_in[5];
    const float* W3        = (const float*)d_in[6];
    float* out = (float*)d_out;

    float *h0, *h1, *u, *v;
    int* hist;
    cudaGetSymbolAddress((void**)&h0, g_h0);
    cudaGetSymbolAddress((void**)&h1, g_h1);
    cudaGetSymbolAddress((void**)&u, g_u);
    cudaGetSymbolAddress((void**)&v, g_v);
    cudaGetSymbolAddress((void**)&hist, g_hist);

    const int G1_SMEM = (DIM_IN * DIM_H + G1_ROWS * DIM_IN) * sizeof(float); // 64KB
    cudaFuncSetAttribute(gemm1_kernel,
                         cudaFuncAttributeMaxDynamicSharedMemorySize, G1_SMEM);

    // One-time infra (created on the correctness call, outside graph capture)
    static cudaStream_t sB = nullptr;
    static cudaEvent_t evFork = nullptr, evJoin = nullptr;
    if (sB == nullptr) {
        cudaStreamCreate(&sB);
        cudaEventCreateWithFlags(&evFork, cudaEventDisableTiming);
        cudaEventCreateWithFlags(&evJoin, cudaEventDisableTiming);
    }

    // Fork: gemm1 on side stream, CSR build on main stream
    cudaEventRecord(evFork, 0);
    cudaStreamWaitEvent(sB, evFork, 0);
    gemm1_kernel<<<(N_NODES + G1_ROWS - 1) / G1_ROWS, 256, G1_SMEM, sB>>>(x, W1);
    cudaEventRecord(evJoin, sB);

    cudaMemsetAsync(hist, 0, N_NODES * sizeof(int));
    hist_kernel<<<(N_EDGES / 4 + 255) / 256, 256>>>(edge_dst);
    scan_all_kernel<<<1, 1024>>>();
    scatter_kernel<<<(N_EDGES / 4 + 255) / 256, 256>>>(edge_src, edge_dst, edge_vals);

    // Join: spmm64 needs h0 (side stream) + CSR (main stream)
    cudaStreamWaitEvent(0, evJoin, 0);
    spmm64_csr_kernel<<<(N_NODES * 16 + 255) / 256, 256>>>(h0, h1);
    gemm2_tanh_kernel<<<(N_NODES + 63) / 64, 256>>>(W2, W3);
    spmm16_csr_kernel<<<(N_NODES * 4 + 255) / 256, 256>>>(u, v);
    spmm16_softmax_kernel<<<(N_NODES * 4 + 255) / 256, 256>>>(v, out);
}

// round 6
// speedup vs baseline: 1.2161x; 1.2161x over previous
#include <cuda_runtime.h>
#include <cuda_bf16.h>
#include <math.h>

#define N_NODES 50000
#define N_EDGES 800000
#define DIM_IN  128
#define DIM_H   64
#define DIM_OUT 16
#define SCAN_BLOCKS ((N_NODES + 1023) / 1024)   // 49

// Scratch (allocation-free: __device__ globals)
__device__ float g_h0[N_NODES * DIM_H];    // x @ W1
__device__ float g_h1[N_NODES * DIM_H];    // spmm1 result (width 64)
__device__ float g_u[N_NODES * DIM_OUT];   // tanh(h1) @ (W2@W3)
__device__ float g_v[N_NODES * DIM_OUT];   // spmm2 result (width 16)

// CSR build scratch
__device__ int                g_hist[N_NODES];
__device__ int                g_row_ptr[N_NODES + 1];
__device__ int                g_cursor[N_NODES];
__device__ int                g_bsum[64];
__device__ unsigned long long g_srt[N_EDGES];   // (val_bits<<32) | src

__device__ __forceinline__ float tanh_fast(float x) {
    float y;
    asm("tanh.approx.f32 %0, %1;" : "=f"(y) : "f"(x));
    return y;
}

// ---- packed f32x2 helpers ----
__device__ __forceinline__ unsigned long long pack2(float a, float b) {
    unsigned long long r;
    asm("mov.b64 %0, {%1, %2};" : "=l"(r) : "f"(a), "f"(b));
    return r;
}
__device__ __forceinline__ void fma2(unsigned long long& d,
                                     unsigned long long a,
                                     unsigned long long b) {
    asm("fma.rn.f32x2 %0, %1, %2, %0;" : "+l"(d) : "l"(a), "l"(b));
}
__device__ __forceinline__ float2 unpack2(unsigned long long v) {
    float2 f;
    asm("mov.b64 {%0, %1}, %2;" : "=f"(f.x), "=f"(f.y) : "l"(v));
    return f;
}

__device__ __forceinline__ void unpack_edge(unsigned long long pr, int& s, float& v) {
    s = (int)(unsigned)(pr & 0xffffffffull);
    v = __uint_as_float((unsigned)(pr >> 32));
}

// ================= CSR build: counting sort by dst =================

__global__ void hist_kernel(const int* __restrict__ dst) {
    int t = blockIdx.x * blockDim.x + threadIdx.x;
    if (t >= N_EDGES / 4) return;
    int4 d = ((const int4*)dst)[t];
    atomicAdd(&g_hist[d.x], 1);
    atomicAdd(&g_hist[d.y], 1);
    atomicAdd(&g_hist[d.z], 1);
    atomicAdd(&g_hist[d.w], 1);
}

// per-1024-chunk exclusive scan; chunk-local result into row_ptr, totals into bsum
__global__ void scan1_kernel() {
    __shared__ int warp_sums[32];
    int tid = threadIdx.x;
    int gid = blockIdx.x * 1024 + tid;
    int lane = tid & 31, wid = tid >> 5;
    int v = (gid < N_NODES) ? g_hist[gid] : 0;
    int incl = v;
#pragma unroll
    for (int o = 1; o < 32; o <<= 1) {
        int n = __shfl_up_sync(0xffffffffu, incl, o);
        if (lane >= o) incl += n;
    }
    if (lane == 31) warp_sums[wid] = incl;
    __syncthreads();
    if (wid == 0) {
        int s = warp_sums[lane];
#pragma unroll
        for (int o = 1; o < 32; o <<= 1) {
            int n = __shfl_up_sync(0xffffffffu, s, o);
            if (lane >= o) s += n;
        }
        warp_sums[lane] = s;
    }
    __syncthreads();
    int warp_off = (wid == 0) ? 0 : warp_sums[wid - 1];
    if (gid < N_NODES) g_row_ptr[gid] = warp_off + incl - v;
    if (tid == 1023) g_bsum[blockIdx.x] = warp_off + incl;
}

// scan the 49 block sums (1 warp)
__global__ void scan2_kernel() {
    int lane = threadIdx.x;
    int total = 0;
    for (int c = 0; c < SCAN_BLOCKS; c += 32) {
        int i = c + lane;
        int v = (i < SCAN_BLOCKS) ? g_bsum[i] : 0;
        int incl = v;
#pragma unroll
        for (int o = 1; o < 32; o <<= 1) {
            int n = __shfl_up_sync(0xffffffffu, incl, o);
            if (lane >= o) incl += n;
        }
        if (i < SCAN_BLOCKS) g_bsum[i] = incl - v + total;
        total += __shfl_sync(0xffffffffu, incl, 31);
    }
    if (lane == 0) g_row_ptr[N_NODES] = total;
}

// fixup: add block offsets; init cursor
__global__ void scan3_kernel() {
    int gid = blockIdx.x * 1024 + threadIdx.x;
    if (gid < N_NODES) {
        int rp = g_row_ptr[gid] + g_bsum[blockIdx.x];
        g_row_ptr[gid] = rp;
        g_cursor[gid] = rp;
    }
}

// scatter edges into dst-sorted order; ONE 8B store per edge
__global__ void scatter_kernel(const int* __restrict__ src,
                               const int* __restrict__ dst,
                               const float* __restrict__ vals) {
    int t = blockIdx.x * blockDim.x + threadIdx.x;
    if (t >= N_EDGES / 4) return;
    int4 s = ((const int4*)src)[t];
    int4 d = ((const int4*)dst)[t];
    float4 v = ((const float4*)vals)[t];
    int p;
    p = atomicAdd(&g_cursor[d.x], 1);
    g_srt[p] = ((unsigned long long)__float_as_uint(v.x) << 32) | (unsigned)s.x;
    p = atomicAdd(&g_cursor[d.y], 1);
    g_srt[p] = ((unsigned long long)__float_as_uint(v.y) << 32) | (unsigned)s.y;
    p = atomicAdd(&g_cursor[d.z], 1);
    g_srt[p] = ((unsigned long long)__float_as_uint(v.z) << 32) | (unsigned)s.z;
    p = atomicAdd(&g_cursor[d.w], 1);
    g_srt[p] = ((unsigned long long)__float_as_uint(v.w) << 32) | (unsigned)s.w;
}

// ================= dense kernels =================

// GEMM1: h0 = x @ W1  (50000x128 @ 128x64), 64-row tile, f32x2
#define G1_ROWS 64
__global__ __launch_bounds__(256) void gemm1_kernel(const float* __restrict__ x,
                                                    const float* __restrict__ W1) {
    extern __shared__ float smem[];
    float4* sW = (float4*)smem;                       // [128][16] float4
    float4* sx = (float4*)(smem + DIM_IN * DIM_H);    // [64][32] float4
    int tid = threadIdx.x;
    int row0 = blockIdx.x * G1_ROWS;

    const float4* W4 = (const float4*)W1;
    for (int i = tid; i < DIM_IN * 16; i += 256) sW[i] = W4[i];
    const float4* x4 = (const float4*)x;
    for (int i = tid; i < G1_ROWS * 32; i += 256) {
        int r = i >> 5, c = i & 31;
        sx[i] = (row0 + r < N_NODES) ? x4[(size_t)(row0 + r) * 32 + c]
                                     : make_float4(0.f, 0.f, 0.f, 0.f);
    }
    __syncthreads();

    int tx = tid & 15;
    int ty = tid >> 4;
    unsigned long long acc[4][2];
#pragma unroll
    for (int i = 0; i < 4; i++) { acc[i][0] = 0ull; acc[i][1] = 0ull; }

    for (int k4 = 0; k4 < DIM_IN / 4; k4++) {
        float4 w0 = sW[(4 * k4 + 0) * 16 + tx];
        float4 w1 = sW[(4 * k4 + 1) * 16 + tx];
        float4 w2 = sW[(4 * k4 + 2) * 16 + tx];
        float4 w3 = sW[(4 * k4 + 3) * 16 + tx];
        unsigned long long w0a = pack2(w0.x, w0.y), w0b = pack2(w0.z, w0.w);
        unsigned long long w1a = pack2(w1.x, w1.y), w1b = pack2(w1.z, w1.w);
        unsigned long long w2a = pack2(w2.x, w2.y), w2b = pack2(w2.z, w2.w);
        unsigned long long w3a = pack2(w3.x, w3.y), w3b = pack2(w3.z, w3.w);
#pragma unroll
        for (int i = 0; i < 4; i++) {
            float4 a = sx[(4 * ty + i) * 32 + k4];
            unsigned long long a0 = pack2(a.x, a.x);
            unsigned long long a1 = pack2(a.y, a.y);
            unsigned long long a2 = pack2(a.z, a.z);
            unsigned long long a3 = pack2(a.w, a.w);
            fma2(acc[i][0], a0, w0a); fma2(acc[i][1], a0, w0b);
            fma2(acc[i][0], a1, w1a); fma2(acc[i][1], a1, w1b);
            fma2(acc[i][0], a2, w2a); fma2(acc[i][1], a2, w2b);
            fma2(acc[i][0], a3, w3a); fma2(acc[i][1], a3, w3b);
        }
    }
#pragma unroll
    for (int i = 0; i < 4; i++) {
        int row = row0 + 4 * ty + i;
        if (row < N_NODES) {
            float2 lo = unpack2(acc[i][0]), hi = unpack2(acc[i][1]);
            ((float4*)(g_h0 + (size_t)row * DIM_H))[tx] =
                make_float4(lo.x, lo.y, hi.x, hi.y);
        }
    }
}

// SPMM width 64, CSR: 16 threads per dst node, 4-edge unroll, 8B pair loads
__global__ __launch_bounds__(256) void spmm64_csr_kernel(const float* __restrict__ h,
                                                         float* __restrict__ out) {
    int t = blockIdx.x * blockDim.x + threadIdx.x;
    int node = t >> 4, c = t & 15;
    if (node >= N_NODES) return;
    int i = g_row_ptr[node], end = g_row_ptr[node + 1];
    float4 acc = make_float4(0.f, 0.f, 0.f, 0.f);
    for (; i + 4 <= end; i += 4) {
        unsigned long long p0 = g_srt[i],     p1 = g_srt[i + 1];
        unsigned long long p2 = g_srt[i + 2], p3 = g_srt[i + 3];
        int s0, s1, s2, s3; float v0, v1, v2, v3;
        unpack_edge(p0, s0, v0); unpack_edge(p1, s1, v1);
        unpack_edge(p2, s2, v2); unpack_edge(p3, s3, v3);
        float4 a0 = ((const float4*)(h + (size_t)s0 * DIM_H))[c];
        float4 a1 = ((const float4*)(h + (size_t)s1 * DIM_H))[c];
        float4 a2 = ((const float4*)(h + (size_t)s2 * DIM_H))[c];
        float4 a3 = ((const float4*)(h + (size_t)s3 * DIM_H))[c];
        acc.x += a0.x * v0; acc.y += a0.y * v0; acc.z += a0.z * v0; acc.w += a0.w * v0;
        acc.x += a1.x * v1; acc.y += a1.y * v1; acc.z += a1.z * v1; acc.w += a1.w * v1;
        acc.x += a2.x * v2; acc.y += a2.y * v2; acc.z += a2.z * v2; acc.w += a2.w * v2;
        acc.x += a3.x * v3; acc.y += a3.y * v3; acc.z += a3.z * v3; acc.w += a3.w * v3;
    }
    for (; i < end; i++) {
        int s0; float v0;
        unpack_edge(g_srt[i], s0, v0);
        float4 a0 = ((const float4*)(h + (size_t)s0 * DIM_H))[c];
        acc.x += a0.x * v0; acc.y += a0.y * v0; acc.z += a0.z * v0; acc.w += a0.w * v0;
    }
    ((float4*)(out + (size_t)node * DIM_H))[c] = acc;
}

// u = tanh(h1) @ (W2@W3): W23 computed in-block, padded smem, f32x2
__global__ __launch_bounds__(256) void gemm2_tanh_kernel(const float* __restrict__ W2,
                                                         const float* __restrict__ W3) {
    __shared__ float sW2[DIM_H * DIM_H];   // 16 KB
    __shared__ float sW3[DIM_H * DIM_OUT]; // 4 KB
    __shared__ float4 sW[DIM_H * 4];       // W23 as [64][4] float4
    __shared__ float sh[64 * 65];          // 16.25 KB
    int tid = threadIdx.x;
    int row0 = blockIdx.x * 64;

    for (int i = tid; i < DIM_H * DIM_H / 4; i += 256)
        ((float4*)sW2)[i] = ((const float4*)W2)[i];
    for (int i = tid; i < DIM_H * DIM_OUT / 4; i += 256)
        ((float4*)sW3)[i] = ((const float4*)W3)[i];
    for (int i = tid; i < 64 * 16; i += 256) {
        int r = i >> 4, k4 = i & 15;
        float4 a = (row0 + r < N_NODES)
            ? ((const float4*)(g_h1 + (size_t)(row0 + r) * DIM_H))[k4]
            : make_float4(0.f, 0.f, 0.f, 0.f);
        float* p = sh + r * 65 + 4 * k4;
        p[0] = tanh_fast(a.x); p[1] = tanh_fast(a.y);
        p[2] = tanh_fast(a.z); p[3] = tanh_fast(a.w);
    }
    __syncthreads();

    // W23 = W2 @ W3: 256 threads, one float4 each (row i, col4 j)
    {
        int i = tid >> 2, j = tid & 3;
        float4 acc = make_float4(0.f, 0.f, 0.f, 0.f);
#pragma unroll 8
        for (int k = 0; k < DIM_H; k++) {
            float a = sW2[i * DIM_H + k];
            float4 w = ((const float4*)sW3)[k * 4 + j];
            acc.x += a * w.x; acc.y += a * w.y;
            acc.z += a * w.z; acc.w += a * w.w;
        }
        sW[i * 4 + j] = acc;
    }
    __syncthreads();

    int r = tid >> 2;
    int c4 = tid & 3;
    unsigned long long acc0 = 0ull, acc1 = 0ull;
#pragma unroll 8
    for (int k = 0; k < DIM_H; k++) {
        float a = sh[r * 65 + k];
        unsigned long long aa = pack2(a, a);
        float4 w = sW[k * 4 + c4];
        fma2(acc0, aa, pack2(w.x, w.y));
        fma2(acc1, aa, pack2(w.z, w.w));
    }
    if (row0 + r < N_NODES) {
        float2 lo = unpack2(acc0), hi = unpack2(acc1);
        ((float4*)(g_u + (size_t)(row0 + r) * DIM_OUT))[c4] =
            make_float4(lo.x, lo.y, hi.x, hi.y);
    }
}

// SPMM width 16, CSR: 4 threads per dst node, 8B pair loads
__global__ __launch_bounds__(256) void spmm16_csr_kernel(const float* __restrict__ h,
                                                         float* __restrict__ out) {
    int t = blockIdx.x * blockDim.x + threadIdx.x;
    int node = t >> 2, c = t & 3;
    if (node >= N_NODES) return;
    int i = g_row_ptr[node], end = g_row_ptr[node + 1];
    float4 acc = make_float4(0.f, 0.f, 0.f, 0.f);
    for (; i + 2 <= end; i += 2) {
        int s0, s1; float v0, v1;
        unpack_edge(g_srt[i], s0, v0);
        unpack_edge(g_srt[i + 1], s1, v1);
        float4 a0 = ((const float4*)(h + (size_t)s0 * DIM_OUT))[c];
        float4 a1 = ((const float4*)(h + (size_t)s1 * DIM_OUT))[c];
        acc.x += a0.x * v0; acc.y += a0.y * v0; acc.z += a0.z * v0; acc.w += a0.w * v0;
        acc.x += a1.x * v1; acc.y += a1.y * v1; acc.z += a1.z * v1; acc.w += a1.w * v1;
    }
    if (i < end) {
        int s0; float v0;
        unpack_edge(g_srt[i], s0, v0);
        float4 a0 = ((const float4*)(h + (size_t)s0 * DIM_OUT))[c];
        acc.x += a0.x * v0; acc.y += a0.y * v0; acc.z += a0.z * v0; acc.w += a0.w * v0;
    }
    ((float4*)(out + (size_t)node * DIM_OUT))[c] = acc;
}

// SPMM width 16 + fused softmax: 4 threads per node, width-4 shfl reduce
__global__ __launch_bounds__(256) void spmm16_softmax_kernel(const float* __restrict__ h,
                                                             float* __restrict__ out) {
    int t = blockIdx.x * blockDim.x + threadIdx.x;
    int node = t >> 2, c = t & 3;
    if (node >= N_NODES) return;
    int i = g_row_ptr[node], end = g_row_ptr[node + 1];
    float4 acc = make_float4(0.f, 0.f, 0.f, 0.f);
    for (; i + 2 <= end; i += 2) {
        int s0, s1; float v0, v1;
        unpack_edge(g_srt[i], s0, v0);
        unpack_edge(g_srt[i + 1], s1, v1);
        float4 a0 = ((const float4*)(h + (size_t)s0 * DIM_OUT))[c];
        float4 a1 = ((const float4*)(h + (size_t)s1 * DIM_OUT))[c];
        acc.x += a0.x * v0; acc.y += a0.y * v0; acc.z += a0.z * v0; acc.w += a0.w * v0;
        acc.x += a1.x * v1; acc.y += a1.y * v1; acc.z += a1.z * v1; acc.w += a1.w * v1;
    }
    if (i < end) {
        int s0; float v0;
        unpack_edge(g_srt[i], s0, v0);
        float4 a0 = ((const float4*)(h + (size_t)s0 * DIM_OUT))[c];
        acc.x += a0.x * v0; acc.y += a0.y * v0; acc.z += a0.z * v0; acc.w += a0.w * v0;
    }
    // softmax across 16 values held by 4 consecutive lanes (4 each)
    float m = fmaxf(fmaxf(acc.x, acc.y), fmaxf(acc.z, acc.w));
    m = fmaxf(m, __shfl_xor_sync(0xffffffffu, m, 1));
    m = fmaxf(m, __shfl_xor_sync(0xffffffffu, m, 2));
    float4 e;
    e.x = __expf(acc.x - m); e.y = __expf(acc.y - m);
    e.z = __expf(acc.z - m); e.w = __expf(acc.w - m);
    float s = e.x + e.y + e.z + e.w;
    s += __shfl_xor_sync(0xffffffffu, s, 1);
    s += __shfl_xor_sync(0xffffffffu, s, 2);
    float inv = __frcp_rn(s);
    ((float4*)(out + (size_t)node * DIM_OUT))[c] =
        make_float4(e.x * inv, e.y * inv, e.z * inv, e.w * inv);
}

extern "C" void kernel_launch(void* const* d_in, const int* in_sizes, int n_in,
                              void* d_out, int out_size) {
    const float* x         = (const float*)d_in[0];
    const int*   edge_src  = (const int*)d_in[1];
    const int*   edge_dst  = (const int*)d_in[2];
    const float* edge_vals = (const float*)d_in[3];
    const float* W1        = (const float*)d_in[4];
    const float* W2        = (const float*)d_in[5];
    const float* W3        = (const float*)d_in[6];
    float* out = (float*)d_out;

    float *h0, *h1, *u, *v;
    int* hist;
    cudaGetSymbolAddress((void**)&h0, g_h0);
    cudaGetSymbolAddress((void**)&h1, g_h1);
    cudaGetSymbolAddress((void**)&u, g_u);
    cudaGetSymbolAddress((void**)&v, g_v);
    cudaGetSymbolAddress((void**)&hist, g_hist);

    const int G1_SMEM = (DIM_IN * DIM_H + G1_ROWS * DIM_IN) * sizeof(float); // 64KB
    cudaFuncSetAttribute(gemm1_kernel,
                         cudaFuncAttributeMaxDynamicSharedMemorySize, G1_SMEM);

    // --- CSR build (counting sort by dst) ---
    cudaMemsetAsync(hist, 0, N_NODES * sizeof(int));
    hist_kernel<<<(N_EDGES / 4 + 255) / 256, 256>>>(edge_dst);
    scan1_kernel<<<SCAN_BLOCKS, 1024>>>();
    scan2_kernel<<<1, 32>>>();
    scan3_kernel<<<SCAN_BLOCKS, 1024>>>();
    scatter_kernel<<<(N_EDGES / 4 + 255) / 256, 256>>>(edge_src, edge_dst, edge_vals);

    // --- dense + SPMM pipeline ---
    gemm1_kernel<<<(N_NODES + G1_ROWS - 1) / G1_ROWS, 256, G1_SMEM>>>(x, W1);
    spmm64_csr_kernel<<<(N_NODES * 16 + 255) / 256, 256>>>(h0, h1);
    gemm2_tanh_kernel<<<(N_NODES + 63) / 64, 256>>>(W2, W3);
    spmm16_csr_kernel<<<(N_NODES * 4 + 255) / 256, 256>>>(u, v);
    spmm16_softmax_kernel<<<(N_NODES * 4 + 255) / 256, 256>>>(v, out);
}

// round 7
// speedup vs baseline: 1.4592x; 1.1999x over previous
#include <cuda_runtime.h>
#include <cuda_bf16.h>
#include <math.h>

#define N_NODES 50000
#define N_EDGES 800000
#define DIM_IN  128
#define DIM_H   64
#define DIM_OUT 16
#define SCAN_BLOCKS ((N_NODES + 1023) / 1024)          // 49
#define G1_ROWS 64
#define GEMM1_BLOCKS ((N_NODES + G1_ROWS - 1) / G1_ROWS)  // 782
#define HIST_BLOCKS ((N_EDGES / 4 + 255) / 256)           // 782

// Scratch (allocation-free: __device__ globals; zero-initialized at load)
__device__ float g_h0[N_NODES * DIM_H];    // x @ W1
__device__ float g_u[N_NODES * DIM_OUT];   // tanh(spmm(h0)) @ (W2@W3)
__device__ float g_v[N_NODES * DIM_OUT];   // spmm2 result (width 16)
__device__ float g_W23[DIM_H * DIM_OUT];   // W2 @ W3 (64x16)

// CSR build scratch
__device__ int                g_hist[N_NODES];     // zero-init; re-zeroed by scan1
__device__ int                g_row_ptr[N_NODES + 1];
__device__ int                g_cursor[N_NODES];
__device__ int                g_bsum[64];
__device__ unsigned long long g_srt[N_EDGES];      // (val_bits<<32) | src

__device__ __forceinline__ float tanh_fast(float x) {
    float y;
    asm("tanh.approx.f32 %0, %1;" : "=f"(y) : "f"(x));
    return y;
}

// ---- packed f32x2 helpers ----
__device__ __forceinline__ unsigned long long pack2(float a, float b) {
    unsigned long long r;
    asm("mov.b64 %0, {%1, %2};" : "=l"(r) : "f"(a), "f"(b));
    return r;
}
__device__ __forceinline__ void fma2(unsigned long long& d,
                                     unsigned long long a,
                                     unsigned long long b) {
    asm("fma.rn.f32x2 %0, %1, %2, %0;" : "+l"(d) : "l"(a), "l"(b));
}
__device__ __forceinline__ float2 unpack2(unsigned long long v) {
    float2 f;
    asm("mov.b64 {%0, %1}, %2;" : "=f"(f.x), "=f"(f.y) : "l"(v));
    return f;
}
__device__ __forceinline__ void unpack_edge(unsigned long long pr, int& s, float& v) {
    s = (int)(unsigned)(pr & 0xffffffffull);
    v = __uint_as_float((unsigned)(pr >> 32));
}

// ================= Kernel A: gemm1 || hist || W23 (independent work) =========
// blocks [0, GEMM1_BLOCKS)                : h0 = x @ W1 (64-row tile, f32x2)
// blocks [GEMM1_BLOCKS, +HIST_BLOCKS)     : histogram of dst
// block  GEMM1_BLOCKS+HIST_BLOCKS (last)  : W23 = W2 @ W3
__global__ __launch_bounds__(256) void kernelA(const float* __restrict__ x,
                                               const float* __restrict__ W1,
                                               const float* __restrict__ W2,
                                               const float* __restrict__ W3,
                                               const int* __restrict__ dst) {
    int tid = threadIdx.x;
    if (blockIdx.x < GEMM1_BLOCKS) {
        // ---- gemm1 ----
        extern __shared__ float smem[];
        float4* sW = (float4*)smem;                       // [128][16] float4
        float4* sx = (float4*)(smem + DIM_IN * DIM_H);    // [64][32] float4
        int row0 = blockIdx.x * G1_ROWS;

        const float4* W4 = (const float4*)W1;
        for (int i = tid; i < DIM_IN * 16; i += 256) sW[i] = W4[i];
        const float4* x4 = (const float4*)x;
        for (int i = tid; i < G1_ROWS * 32; i += 256) {
            int r = i >> 5, c = i & 31;
            sx[i] = (row0 + r < N_NODES) ? x4[(size_t)(row0 + r) * 32 + c]
                                         : make_float4(0.f, 0.f, 0.f, 0.f);
        }
        __syncthreads();

        int tx = tid & 15;
        int ty = tid >> 4;
        unsigned long long acc[4][2];
#pragma unroll
        for (int i = 0; i < 4; i++) { acc[i][0] = 0ull; acc[i][1] = 0ull; }

        for (int k4 = 0; k4 < DIM_IN / 4; k4++) {
            float4 w0 = sW[(4 * k4 + 0) * 16 + tx];
            float4 w1 = sW[(4 * k4 + 1) * 16 + tx];
            float4 w2 = sW[(4 * k4 + 2) * 16 + tx];
            float4 w3 = sW[(4 * k4 + 3) * 16 + tx];
            unsigned long long w0a = pack2(w0.x, w0.y), w0b = pack2(w0.z, w0.w);
            unsigned long long w1a = pack2(w1.x, w1.y), w1b = pack2(w1.z, w1.w);
            unsigned long long w2a = pack2(w2.x, w2.y), w2b = pack2(w2.z, w2.w);
            unsigned long long w3a = pack2(w3.x, w3.y), w3b = pack2(w3.z, w3.w);
#pragma unroll
            for (int i = 0; i < 4; i++) {
                float4 a = sx[(4 * ty + i) * 32 + k4];
                unsigned long long a0 = pack2(a.x, a.x);
                unsigned long long a1 = pack2(a.y, a.y);
                unsigned long long a2 = pack2(a.z, a.z);
                unsigned long long a3 = pack2(a.w, a.w);
                fma2(acc[i][0], a0, w0a); fma2(acc[i][1], a0, w0b);
                fma2(acc[i][0], a1, w1a); fma2(acc[i][1], a1, w1b);
                fma2(acc[i][0], a2, w2a); fma2(acc[i][1], a2, w2b);
                fma2(acc[i][0], a3, w3a); fma2(acc[i][1], a3, w3b);
            }
        }
#pragma unroll
        for (int i = 0; i < 4; i++) {
            int row = row0 + 4 * ty + i;
            if (row < N_NODES) {
                float2 lo = unpack2(acc[i][0]), hi = unpack2(acc[i][1]);
                ((float4*)(g_h0 + (size_t)row * DIM_H))[tx] =
                    make_float4(lo.x, lo.y, hi.x, hi.y);
            }
        }
    } else if (blockIdx.x < GEMM1_BLOCKS + HIST_BLOCKS) {
        // ---- histogram of dst ----
        int t = (blockIdx.x - GEMM1_BLOCKS) * 256 + tid;
        if (t < N_EDGES / 4) {
            int4 d = ((const int4*)dst)[t];
            atomicAdd(&g_hist[d.x], 1);
            atomicAdd(&g_hist[d.y], 1);
            atomicAdd(&g_hist[d.z], 1);
            atomicAdd(&g_hist[d.w], 1);
        }
    } else {
        // ---- W23 = W2 @ W3 ----
        for (int o = tid; o < DIM_H * DIM_OUT; o += 256) {
            int i = o >> 4, j = o & 15;
            float acc = 0.0f;
#pragma unroll 8
            for (int k = 0; k < DIM_H; k++)
                acc += W2[i * DIM_H + k] * W3[k * DIM_OUT + j];
            g_W23[o] = acc;
        }
    }
}

// ================= CSR build: scan + scatter =================

// per-1024-chunk exclusive scan; local result into row_ptr, totals into bsum.
// Also re-zeros g_hist for the next replay.
__global__ __launch_bounds__(1024) void scan1_kernel() {
    __shared__ int warp_sums[32];
    int tid = threadIdx.x;
    int gid = blockIdx.x * 1024 + tid;
    int lane = tid & 31, wid = tid >> 5;
    int v = (gid < N_NODES) ? g_hist[gid] : 0;
    if (gid < N_NODES) g_hist[gid] = 0;   // leave zeroed (deterministic per-call)
    int incl = v;
#pragma unroll
    for (int o = 1; o < 32; o <<= 1) {
        int n = __shfl_up_sync(0xffffffffu, incl, o);
        if (lane >= o) incl += n;
    }
    if (lane == 31) warp_sums[wid] = incl;
    __syncthreads();
    if (wid == 0) {
        int s = warp_sums[lane];
#pragma unroll
        for (int o = 1; o < 32; o <<= 1) {
            int n = __shfl_up_sync(0xffffffffu, s, o);
            if (lane >= o) s += n;
        }
        warp_sums[lane] = s;
    }
    __syncthreads();
    int warp_off = (wid == 0) ? 0 : warp_sums[wid - 1];
    if (gid < N_NODES) g_row_ptr[gid] = warp_off + incl - v;
    if (tid == 1023) g_bsum[blockIdx.x] = warp_off + incl;
}

// fused scan of block sums + offset fixup + cursor init.
// Each block redundantly scans the 49 bsums in smem (cheap), applies its own offset.
__global__ __launch_bounds__(1024) void scan23_kernel() {
    __shared__ int sb[64];
    __shared__ int s_total;
    int tid = threadIdx.x;
    if (tid < 64) sb[tid] = (tid < SCAN_BLOCKS) ? g_bsum[tid] : 0;
    __syncthreads();
    if (tid < 32) {
        int v0 = sb[tid], v1 = sb[tid + 32];
        int i0 = v0;
#pragma unroll
        for (int o = 1; o < 32; o <<= 1) {
            int n = __shfl_up_sync(0xffffffffu, i0, o);
            if (tid >= o) i0 += n;
        }
        int t0 = __shfl_sync(0xffffffffu, i0, 31);
        int i1 = v1;
#pragma unroll
        for (int o = 1; o < 32; o <<= 1) {
            int n = __shfl_up_sync(0xffffffffu, i1, o);
            if (tid >= o) i1 += n;
        }
        int t1 = __shfl_sync(0xffffffffu, i1, 31);
        sb[tid] = i0 - v0;                 // exclusive
        sb[tid + 32] = i1 - v1 + t0;
        if (tid == 0) s_total = t0 + t1;
    }
    __syncthreads();
    int offset = sb[blockIdx.x];
    int gid = blockIdx.x * 1024 + tid;
    if (gid < N_NODES) {
        int rp = g_row_ptr[gid] + offset;
        g_row_ptr[gid] = rp;
        g_cursor[gid] = rp;
    }
    if (blockIdx.x == 0 && tid == 0) g_row_ptr[N_NODES] = s_total;
}

// scatter edges into dst-sorted order; ONE 8B store per edge
__global__ void scatter_kernel(const int* __restrict__ src,
                               const int* __restrict__ dst,
                               const float* __restrict__ vals) {
    int t = blockIdx.x * blockDim.x + threadIdx.x;
    if (t >= N_EDGES / 4) return;
    int4 s = ((const int4*)src)[t];
    int4 d = ((const int4*)dst)[t];
    float4 v = ((const float4*)vals)[t];
    int p;
    p = atomicAdd(&g_cursor[d.x], 1);
    g_srt[p] = ((unsigned long long)__float_as_uint(v.x) << 32) | (unsigned)s.x;
    p = atomicAdd(&g_cursor[d.y], 1);
    g_srt[p] = ((unsigned long long)__float_as_uint(v.y) << 32) | (unsigned)s.y;
    p = atomicAdd(&g_cursor[d.z], 1);
    g_srt[p] = ((unsigned long long)__float_as_uint(v.z) << 32) | (unsigned)s.z;
    p = atomicAdd(&g_cursor[d.w], 1);
    g_srt[p] = ((unsigned long long)__float_as_uint(v.w) << 32) | (unsigned)s.w;
}

// ======= layer2: u = tanh(spmm64(h0)) @ W23, fully fused per 16-node tile ====
// 256 threads = 16 nodes x 16 chunks. Phase1: CSR accumulate + tanh -> smem.
// Phase2: 16x16 GEMM tile vs W23 -> g_u (coalesced: index = node0*16 + tid).
__global__ __launch_bounds__(256) void layer2_kernel(const float* __restrict__ h) {
    __shared__ float sh[16 * 65];             // padded: conflict-free
    __shared__ float sW[DIM_H * DIM_OUT];     // W23 [64][16]
    int tid = threadIdx.x;
    for (int i = tid; i < DIM_H * DIM_OUT / 4; i += 256)
        ((float4*)sW)[i] = ((const float4*)g_W23)[i];

    int node0 = blockIdx.x * 16;
    int r = tid >> 4;          // node within tile
    int c = tid & 15;          // float4 chunk of width-64 row
    int node = node0 + r;      // 3125*16 == 50000 exactly

    int i = g_row_ptr[node], end = g_row_ptr[node + 1];
    float4 acc = make_float4(0.f, 0.f, 0.f, 0.f);
    for (; i + 4 <= end; i += 4) {
        unsigned long long p0 = g_srt[i],     p1 = g_srt[i + 1];
        unsigned long long p2 = g_srt[i + 2], p3 = g_srt[i + 3];
        int s0, s1, s2, s3; float v0, v1, v2, v3;
        unpack_edge(p0, s0, v0); unpack_edge(p1, s1, v1);
        unpack_edge(p2, s2, v2); unpack_edge(p3, s3, v3);
        float4 a0 = ((const float4*)(h + (size_t)s0 * DIM_H))[c];
        float4 a1 = ((const float4*)(h + (size_t)s1 * DIM_H))[c];
        float4 a2 = ((const float4*)(h + (size_t)s2 * DIM_H))[c];
        float4 a3 = ((const float4*)(h + (size_t)s3 * DIM_H))[c];
        acc.x += a0.x * v0; acc.y += a0.y * v0; acc.z += a0.z * v0; acc.w += a0.w * v0;
        acc.x += a1.x * v1; acc.y += a1.y * v1; acc.z += a1.z * v1; acc.w += a1.w * v1;
        acc.x += a2.x * v2; acc.y += a2.y * v2; acc.z += a2.z * v2; acc.w += a2.w * v2;
        acc.x += a3.x * v3; acc.y += a3.y * v3; acc.z += a3.z * v3; acc.w += a3.w * v3;
    }
    for (; i < end; i++) {
        int s0; float v0;
        unpack_edge(g_srt[i], s0, v0);
        float4 a0 = ((const float4*)(h + (size_t)s0 * DIM_H))[c];
        acc.x += a0.x * v0; acc.y += a0.y * v0; acc.z += a0.z * v0; acc.w += a0.w * v0;
    }
    float* p = sh + r * 65 + c * 4;
    p[0] = tanh_fast(acc.x); p[1] = tanh_fast(acc.y);
    p[2] = tanh_fast(acc.z); p[3] = tanh_fast(acc.w);
    __syncthreads();

    // phase2: row = tid>>4 (0..15), col = tid&15
    int row = tid >> 4, col = tid & 15;
    float a = 0.0f;
#pragma unroll 8
    for (int k = 0; k < DIM_H; k++)
        a += sh[row * 65 + k] * sW[k * DIM_OUT + col];
    g_u[(size_t)node0 * DIM_OUT + tid] = a;
}

// SPMM width 16, CSR: 4 threads per dst node, 8B pair loads
__global__ __launch_bounds__(256) void spmm16_csr_kernel(const float* __restrict__ h,
                                                         float* __restrict__ out) {
    int t = blockIdx.x * blockDim.x + threadIdx.x;
    int node = t >> 2, c = t & 3;
    if (node >= N_NODES) return;
    int i = g_row_ptr[node], end = g_row_ptr[node + 1];
    float4 acc = make_float4(0.f, 0.f, 0.f, 0.f);
    for (; i + 2 <= end; i += 2) {
        int s0, s1; float v0, v1;
        unpack_edge(g_srt[i], s0, v0);
        unpack_edge(g_srt[i + 1], s1, v1);
        float4 a0 = ((const float4*)(h + (size_t)s0 * DIM_OUT))[c];
        float4 a1 = ((const float4*)(h + (size_t)s1 * DIM_OUT))[c];
        acc.x += a0.x * v0; acc.y += a0.y * v0; acc.z += a0.z * v0; acc.w += a0.w * v0;
        acc.x += a1.x * v1; acc.y += a1.y * v1; acc.z += a1.z * v1; acc.w += a1.w * v1;
    }
    if (i < end) {
        int s0; float v0;
        unpack_edge(g_srt[i], s0, v0);
        float4 a0 = ((const float4*)(h + (size_t)s0 * DIM_OUT))[c];
        acc.x += a0.x * v0; acc.y += a0.y * v0; acc.z += a0.z * v0; acc.w += a0.w * v0;
    }
    ((float4*)(out + (size_t)node * DIM_OUT))[c] = acc;
}

// SPMM width 16 + fused softmax: 4 threads per node, width-4 shfl reduce
__global__ __launch_bounds__(256) void spmm16_softmax_kernel(const float* __restrict__ h,
                                                             float* __restrict__ out) {
    int t = blockIdx.x * blockDim.x + threadIdx.x;
    int node = t >> 2, c = t & 3;
    if (node >= N_NODES) return;
    int i = g_row_ptr[node], end = g_row_ptr[node + 1];
    float4 acc = make_float4(0.f, 0.f, 0.f, 0.f);
    for (; i + 2 <= end; i += 2) {
        int s0, s1; float v0, v1;
        unpack_edge(g_srt[i], s0, v0);
        unpack_edge(g_srt[i + 1], s1, v1);
        float4 a0 = ((const float4*)(h + (size_t)s0 * DIM_OUT))[c];
        float4 a1 = ((const float4*)(h + (size_t)s1 * DIM_OUT))[c];
        acc.x += a0.x * v0; acc.y += a0.y * v0; acc.z += a0.z * v0; acc.w += a0.w * v0;
        acc.x += a1.x * v1; acc.y += a1.y * v1; acc.z += a1.z * v1; acc.w += a1.w * v1;
    }
    if (i < end) {
        int s0; float v0;
        unpack_edge(g_srt[i], s0, v0);
        float4 a0 = ((const float4*)(h + (size_t)s0 * DIM_OUT))[c];
        acc.x += a0.x * v0; acc.y += a0.y * v0; acc.z += a0.z * v0; acc.w += a0.w * v0;
    }
    float m = fmaxf(fmaxf(acc.x, acc.y), fmaxf(acc.z, acc.w));
    m = fmaxf(m, __shfl_xor_sync(0xffffffffu, m, 1));
    m = fmaxf(m, __shfl_xor_sync(0xffffffffu, m, 2));
    float4 e;
    e.x = __expf(acc.x - m); e.y = __expf(acc.y - m);
    e.z = __expf(acc.z - m); e.w = __expf(acc.w - m);
    float s = e.x + e.y + e.z + e.w;
    s += __shfl_xor_sync(0xffffffffu, s, 1);
    s += __shfl_xor_sync(0xffffffffu, s, 2);
    float inv = __frcp_rn(s);
    ((float4*)(out + (size_t)node * DIM_OUT))[c] =
        make_float4(e.x * inv, e.y * inv, e.z * inv, e.w * inv);
}

extern "C" void kernel_launch(void* const* d_in, const int* in_sizes, int n_in,
                              void* d_out, int out_size) {
    const float* x         = (const float*)d_in[0];
    const int*   edge_src  = (const int*)d_in[1];
    const int*   edge_dst  = (const int*)d_in[2];
    const float* edge_vals = (const float*)d_in[3];
    const float* W1        = (const float*)d_in[4];
    const float* W2        = (const float*)d_in[5];
    const float* W3        = (const float*)d_in[6];
    float* out = (float*)d_out;

    float *h0, *u, *v;
    cudaGetSymbolAddress((void**)&h0, g_h0);
    cudaGetSymbolAddress((void**)&u, g_u);
    cudaGetSymbolAddress((void**)&v, g_v);

    const int G1_SMEM = (DIM_IN * DIM_H + G1_ROWS * DIM_IN) * sizeof(float); // 64KB
    cudaFuncSetAttribute(kernelA,
                         cudaFuncAttributeMaxDynamicSharedMemorySize, G1_SMEM);

    // 1. gemm1 || hist || W23
    kernelA<<<GEMM1_BLOCKS + HIST_BLOCKS + 1, 256, G1_SMEM>>>(x, W1, W2, W3, edge_dst);

    // 2-4. CSR build
    scan1_kernel<<<SCAN_BLOCKS, 1024>>>();
    scan23_kernel<<<SCAN_BLOCKS, 1024>>>();
    scatter_kernel<<<(N_EDGES / 4 + 255) / 256, 256>>>(edge_src, edge_dst, edge_vals);

    // 5. u = tanh(spmm64(h0)) @ W23  (fused)
    layer2_kernel<<<N_NODES / 16, 256>>>(h0);

    // 6. v = spmm16(u)
    spmm16_csr_kernel<<<(N_NODES * 4 + 255) / 256, 256>>>(u, v);

    // 7. out = softmax(spmm16(v))
    spmm16_softmax_kernel<<<(N_NODES * 4 + 255) / 256, 256>>>(v, out);
}

// round 8
// speedup vs baseline: 1.4634x; 1.0029x over previous
#include <cuda_runtime.h>
#include <cuda_bf16.h>
#include <math.h>

#define N_NODES 50000
#define N_EDGES 800000
#define DIM_IN  128
#define DIM_H   64
#define DIM_OUT 16
#define SCAN_BLOCKS ((N_NODES + 1023) / 1024)          // 49
#define G1_ROWS 64
#define GEMM1_BLOCKS ((N_NODES + G1_ROWS - 1) / G1_ROWS)  // 782
#define HIST_BLOCKS ((N_EDGES / 4 + 255) / 256)           // 782

// Scratch (allocation-free: __device__ globals; zero-initialized at load)
__device__ float g_h0[N_NODES * DIM_H];    // x @ W1
__device__ float g_u[N_NODES * DIM_OUT];   // tanh(spmm(h0)) @ (W2@W3)
__device__ float g_v[N_NODES * DIM_OUT];   // spmm2 result (width 16)
__device__ float g_W23[DIM_H * DIM_OUT];   // W2 @ W3 (64x16)

// CSR build scratch
__device__ int                g_hist[N_NODES];     // zero-init; re-zeroed by scan1
__device__ int                g_rank[N_EDGES];     // per-edge rank within dst bucket
__device__ int                g_row_ptr[N_NODES + 1];
__device__ int                g_bsum[64];
__device__ unsigned long long g_srt[N_EDGES];      // (val_bits<<32) | src

__device__ __forceinline__ float tanh_fast(float x) {
    float y;
    asm("tanh.approx.f32 %0, %1;" : "=f"(y) : "f"(x));
    return y;
}

// ---- packed f32x2 helpers ----
__device__ __forceinline__ unsigned long long pack2(float a, float b) {
    unsigned long long r;
    asm("mov.b64 %0, {%1, %2};" : "=l"(r) : "f"(a), "f"(b));
    return r;
}
__device__ __forceinline__ void fma2(unsigned long long& d,
                                     unsigned long long a,
                                     unsigned long long b) {
    asm("fma.rn.f32x2 %0, %1, %2, %0;" : "+l"(d) : "l"(a), "l"(b));
}
__device__ __forceinline__ float2 unpack2(unsigned long long v) {
    float2 f;
    asm("mov.b64 {%0, %1}, %2;" : "=f"(f.x), "=f"(f.y) : "l"(v));
    return f;
}
__device__ __forceinline__ void unpack_edge(unsigned long long pr, int& s, float& v) {
    s = (int)(unsigned)(pr & 0xffffffffull);
    v = __uint_as_float((unsigned)(pr >> 32));
}

// ================= Kernel A: gemm1 || hist+rank || W23 =======================
// blocks [0, GEMM1_BLOCKS)                : h0 = x @ W1 (64-row tile, f32x2)
// blocks [GEMM1_BLOCKS, +HIST_BLOCKS)     : histogram of dst + per-edge rank
// block  GEMM1_BLOCKS+HIST_BLOCKS (last)  : W23 = W2 @ W3
__global__ __launch_bounds__(256) void kernelA(const float* __restrict__ x,
                                               const float* __restrict__ W1,
                                               const float* __restrict__ W2,
                                               const float* __restrict__ W3,
                                               const int* __restrict__ dst) {
    int tid = threadIdx.x;
    if (blockIdx.x < GEMM1_BLOCKS) {
        // ---- gemm1 ----
        extern __shared__ float smem[];
        float4* sW = (float4*)smem;                       // [128][16] float4
        float4* sx = (float4*)(smem + DIM_IN * DIM_H);    // [64][32] float4
        int row0 = blockIdx.x * G1_ROWS;

        const float4* W4 = (const float4*)W1;
        for (int i = tid; i < DIM_IN * 16; i += 256) sW[i] = W4[i];
        const float4* x4 = (const float4*)x;
        for (int i = tid; i < G1_ROWS * 32; i += 256) {
            int r = i >> 5, c = i & 31;
            sx[i] = (row0 + r < N_NODES) ? x4[(size_t)(row0 + r) * 32 + c]
                                         : make_float4(0.f, 0.f, 0.f, 0.f);
        }
        __syncthreads();

        int tx = tid & 15;
        int ty = tid >> 4;
        unsigned long long acc[4][2];
#pragma unroll
        for (int i = 0; i < 4; i++) { acc[i][0] = 0ull; acc[i][1] = 0ull; }

        for (int k4 = 0; k4 < DIM_IN / 4; k4++) {
            float4 w0 = sW[(4 * k4 + 0) * 16 + tx];
            float4 w1 = sW[(4 * k4 + 1) * 16 + tx];
            float4 w2 = sW[(4 * k4 + 2) * 16 + tx];
            float4 w3 = sW[(4 * k4 + 3) * 16 + tx];
            unsigned long long w0a = pack2(w0.x, w0.y), w0b = pack2(w0.z, w0.w);
            unsigned long long w1a = pack2(w1.x, w1.y), w1b = pack2(w1.z, w1.w);
            unsigned long long w2a = pack2(w2.x, w2.y), w2b = pack2(w2.z, w2.w);
            unsigned long long w3a = pack2(w3.x, w3.y), w3b = pack2(w3.z, w3.w);
#pragma unroll
            for (int i = 0; i < 4; i++) {
                float4 a = sx[(4 * ty + i) * 32 + k4];
                unsigned long long a0 = pack2(a.x, a.x);
                unsigned long long a1 = pack2(a.y, a.y);
                unsigned long long a2 = pack2(a.z, a.z);
                unsigned long long a3 = pack2(a.w, a.w);
                fma2(acc[i][0], a0, w0a); fma2(acc[i][1], a0, w0b);
                fma2(acc[i][0], a1, w1a); fma2(acc[i][1], a1, w1b);
                fma2(acc[i][0], a2, w2a); fma2(acc[i][1], a2, w2b);
                fma2(acc[i][0], a3, w3a); fma2(acc[i][1], a3, w3b);
            }
        }
#pragma unroll
        for (int i = 0; i < 4; i++) {
            int row = row0 + 4 * ty + i;
            if (row < N_NODES) {
                float2 lo = unpack2(acc[i][0]), hi = unpack2(acc[i][1]);
                ((float4*)(g_h0 + (size_t)row * DIM_H))[tx] =
                    make_float4(lo.x, lo.y, hi.x, hi.y);
            }
        }
    } else if (blockIdx.x < GEMM1_BLOCKS + HIST_BLOCKS) {
        // ---- histogram of dst + per-edge rank capture ----
        int t = (blockIdx.x - GEMM1_BLOCKS) * 256 + tid;
        if (t < N_EDGES / 4) {
            int4 d = ((const int4*)dst)[t];
            int4 r;
            r.x = atomicAdd(&g_hist[d.x], 1);
            r.y = atomicAdd(&g_hist[d.y], 1);
            r.z = atomicAdd(&g_hist[d.z], 1);
            r.w = atomicAdd(&g_hist[d.w], 1);
            ((int4*)g_rank)[t] = r;
        }
    } else {
        // ---- W23 = W2 @ W3 ----
        for (int o = tid; o < DIM_H * DIM_OUT; o += 256) {
            int i = o >> 4, j = o & 15;
            float acc = 0.0f;
#pragma unroll 8
            for (int k = 0; k < DIM_H; k++)
                acc += W2[i * DIM_H + k] * W3[k * DIM_OUT + j];
            g_W23[o] = acc;
        }
    }
}

// ================= CSR build: scan + scatter =================

// per-1024-chunk exclusive scan; local result into row_ptr, totals into bsum.
// Also re-zeros g_hist for the next replay.
__global__ __launch_bounds__(1024) void scan1_kernel() {
    __shared__ int warp_sums[32];
    int tid = threadIdx.x;
    int gid = blockIdx.x * 1024 + tid;
    int lane = tid & 31, wid = tid >> 5;
    int v = (gid < N_NODES) ? g_hist[gid] : 0;
    if (gid < N_NODES) g_hist[gid] = 0;   // leave zeroed (deterministic per-call)
    int incl = v;
#pragma unroll
    for (int o = 1; o < 32; o <<= 1) {
        int n = __shfl_up_sync(0xffffffffu, incl, o);
        if (lane >= o) incl += n;
    }
    if (lane == 31) warp_sums[wid] = incl;
    __syncthreads();
    if (wid == 0) {
        int s = warp_sums[lane];
#pragma unroll
        for (int o = 1; o < 32; o <<= 1) {
            int n = __shfl_up_sync(0xffffffffu, s, o);
            if (lane >= o) s += n;
        }
        warp_sums[lane] = s;
    }
    __syncthreads();
    int warp_off = (wid == 0) ? 0 : warp_sums[wid - 1];
    if (gid < N_NODES) g_row_ptr[gid] = warp_off + incl - v;
    if (tid == 1023) g_bsum[blockIdx.x] = warp_off + incl;
}

// fused scan of block sums + offset fixup.
__global__ __launch_bounds__(1024) void scan23_kernel() {
    __shared__ int sb[64];
    __shared__ int s_total;
    int tid = threadIdx.x;
    if (tid < 64) sb[tid] = (tid < SCAN_BLOCKS) ? g_bsum[tid] : 0;
    __syncthreads();
    if (tid < 32) {
        int v0 = sb[tid], v1 = sb[tid + 32];
        int i0 = v0;
#pragma unroll
        for (int o = 1; o < 32; o <<= 1) {
            int n = __shfl_up_sync(0xffffffffu, i0, o);
            if (tid >= o) i0 += n;
        }
        int t0 = __shfl_sync(0xffffffffu, i0, 31);
        int i1 = v1;
#pragma unroll
        for (int o = 1; o < 32; o <<= 1) {
            int n = __shfl_up_sync(0xffffffffu, i1, o);
            if (tid >= o) i1 += n;
        }
        int t1 = __shfl_sync(0xffffffffu, i1, 31);
        sb[tid] = i0 - v0;                 // exclusive
        sb[tid + 32] = i1 - v1 + t0;
        if (tid == 0) s_total = t0 + t1;
    }
    __syncthreads();
    int offset = sb[blockIdx.x];
    int gid = blockIdx.x * 1024 + tid;
    if (gid < N_NODES) g_row_ptr[gid] += offset;
    if (blockIdx.x == 0 && tid == 0) g_row_ptr[N_NODES] = s_total;
}

// scatter edges into dst-sorted order; NO atomics: p = row_ptr[dst] + rank
__global__ void scatter_kernel(const int* __restrict__ src,
                               const int* __restrict__ dst,
                               const float* __restrict__ vals) {
    int t = blockIdx.x * blockDim.x + threadIdx.x;
    if (t >= N_EDGES / 4) return;
    int4 s = ((const int4*)src)[t];
    int4 d = ((const int4*)dst)[t];
    float4 v = ((const float4*)vals)[t];
    int4 rk = ((const int4*)g_rank)[t];
    int p0 = g_row_ptr[d.x] + rk.x;
    int p1 = g_row_ptr[d.y] + rk.y;
    int p2 = g_row_ptr[d.z] + rk.z;
    int p3 = g_row_ptr[d.w] + rk.w;
    g_srt[p0] = ((unsigned long long)__float_as_uint(v.x) << 32) | (unsigned)s.x;
    g_srt[p1] = ((unsigned long long)__float_as_uint(v.y) << 32) | (unsigned)s.y;
    g_srt[p2] = ((unsigned long long)__float_as_uint(v.z) << 32) | (unsigned)s.z;
    g_srt[p3] = ((unsigned long long)__float_as_uint(v.w) << 32) | (unsigned)s.w;
}

// ======= layer2: u = tanh(spmm64(h0)) @ W23, fused per 16-node tile ==========
__global__ __launch_bounds__(256) void layer2_kernel(const float* __restrict__ h) {
    __shared__ float sh[16 * 65];             // padded: conflict-free
    __shared__ float sW[DIM_H * DIM_OUT];     // W23 [64][16]
    int tid = threadIdx.x;
    for (int i = tid; i < DIM_H * DIM_OUT / 4; i += 256)
        ((float4*)sW)[i] = ((const float4*)g_W23)[i];

    int node0 = blockIdx.x * 16;
    int r = tid >> 4;
    int c = tid & 15;
    int node = node0 + r;

    int i = g_row_ptr[node], end = g_row_ptr[node + 1];
    float4 acc = make_float4(0.f, 0.f, 0.f, 0.f);
    for (; i + 4 <= end; i += 4) {
        unsigned long long p0 = g_srt[i],     p1 = g_srt[i + 1];
        unsigned long long p2 = g_srt[i + 2], p3 = g_srt[i + 3];
        int s0, s1, s2, s3; float v0, v1, v2, v3;
        unpack_edge(p0, s0, v0); unpack_edge(p1, s1, v1);
        unpack_edge(p2, s2, v2); unpack_edge(p3, s3, v3);
        float4 a0 = ((const float4*)(h + (size_t)s0 * DIM_H))[c];
        float4 a1 = ((const float4*)(h + (size_t)s1 * DIM_H))[c];
        float4 a2 = ((const float4*)(h + (size_t)s2 * DIM_H))[c];
        float4 a3 = ((const float4*)(h + (size_t)s3 * DIM_H))[c];
        acc.x += a0.x * v0; acc.y += a0.y * v0; acc.z += a0.z * v0; acc.w += a0.w * v0;
        acc.x += a1.x * v1; acc.y += a1.y * v1; acc.z += a1.z * v1; acc.w += a1.w * v1;
        acc.x += a2.x * v2; acc.y += a2.y * v2; acc.z += a2.z * v2; acc.w += a2.w * v2;
        acc.x += a3.x * v3; acc.y += a3.y * v3; acc.z += a3.z * v3; acc.w += a3.w * v3;
    }
    for (; i < end; i++) {
        int s0; float v0;
        unpack_edge(g_srt[i], s0, v0);
        float4 a0 = ((const float4*)(h + (size_t)s0 * DIM_H))[c];
        acc.x += a0.x * v0; acc.y += a0.y * v0; acc.z += a0.z * v0; acc.w += a0.w * v0;
    }
    float* p = sh + r * 65 + c * 4;
    p[0] = tanh_fast(acc.x); p[1] = tanh_fast(acc.y);
    p[2] = tanh_fast(acc.z); p[3] = tanh_fast(acc.w);
    __syncthreads();

    int row = tid >> 4, col = tid & 15;
    float a = 0.0f;
#pragma unroll 8
    for (int k = 0; k < DIM_H; k++)
        a += sh[row * 65 + k] * sW[k * DIM_OUT + col];
    g_u[(size_t)node0 * DIM_OUT + tid] = a;
}

// SPMM width 16, CSR: 4 threads per dst node, 8B pair loads
__global__ __launch_bounds__(256) void spmm16_csr_kernel(const float* __restrict__ h,
                                                         float* __restrict__ out) {
    int t = blockIdx.x * blockDim.x + threadIdx.x;
    int node = t >> 2, c = t & 3;
    if (node >= N_NODES) return;
    int i = g_row_ptr[node], end = g_row_ptr[node + 1];
    float4 acc = make_float4(0.f, 0.f, 0.f, 0.f);
    for (; i + 2 <= end; i += 2) {
        int s0, s1; float v0, v1;
        unpack_edge(g_srt[i], s0, v0);
        unpack_edge(g_srt[i + 1], s1, v1);
        float4 a0 = ((const float4*)(h + (size_t)s0 * DIM_OUT))[c];
        float4 a1 = ((const float4*)(h + (size_t)s1 * DIM_OUT))[c];
        acc.x += a0.x * v0; acc.y += a0.y * v0; acc.z += a0.z * v0; acc.w += a0.w * v0;
        acc.x += a1.x * v1; acc.y += a1.y * v1; acc.z += a1.z * v1; acc.w += a1.w * v1;
    }
    if (i < end) {
        int s0; float v0;
        unpack_edge(g_srt[i], s0, v0);
        float4 a0 = ((const float4*)(h + (size_t)s0 * DIM_OUT))[c];
        acc.x += a0.x * v0; acc.y += a0.y * v0; acc.z += a0.z * v0; acc.w += a0.w * v0;
    }
    ((float4*)(out + (size_t)node * DIM_OUT))[c] = acc;
}

// SPMM width 16 + fused softmax: 4 threads per node, width-4 shfl reduce
__global__ __launch_bounds__(256) void spmm16_softmax_kernel(const float* __restrict__ h,
                                                             float* __restrict__ out) {
    int t = blockIdx.x * blockDim.x + threadIdx.x;
    int node = t >> 2, c = t & 3;
    if (node >= N_NODES) return;
    int i = g_row_ptr[node], end = g_row_ptr[node + 1];
    float4 acc = make_float4(0.f, 0.f, 0.f, 0.f);
    for (; i + 2 <= end; i += 2) {
        int s0, s1; float v0, v1;
        unpack_edge(g_srt[i], s0, v0);
        unpack_edge(g_srt[i + 1], s1, v1);
        float4 a0 = ((const float4*)(h + (size_t)s0 * DIM_OUT))[c];
        float4 a1 = ((const float4*)(h + (size_t)s1 * DIM_OUT))[c];
        acc.x += a0.x * v0; acc.y += a0.y * v0; acc.z += a0.z * v0; acc.w += a0.w * v0;
        acc.x += a1.x * v1; acc.y += a1.y * v1; acc.z += a1.z * v1; acc.w += a1.w * v1;
    }
    if (i < end) {
        int s0; float v0;
        unpack_edge(g_srt[i], s0, v0);
        float4 a0 = ((const float4*)(h + (size_t)s0 * DIM_OUT))[c];
        acc.x += a0.x * v0; acc.y += a0.y * v0; acc.z += a0.z * v0; acc.w += a0.w * v0;
    }
    float m = fmaxf(fmaxf(acc.x, acc.y), fmaxf(acc.z, acc.w));
    m = fmaxf(m, __shfl_xor_sync(0xffffffffu, m, 1));
    m = fmaxf(m, __shfl_xor_sync(0xffffffffu, m, 2));
    float4 e;
    e.x = __expf(acc.x - m); e.y = __expf(acc.y - m);
    e.z = __expf(acc.z - m); e.w = __expf(acc.w - m);
    float s = e.x + e.y + e.z + e.w;
    s += __shfl_xor_sync(0xffffffffu, s, 1);
    s += __shfl_xor_sync(0xffffffffu, s, 2);
    float inv = __frcp_rn(s);
    ((float4*)(out + (size_t)node * DIM_OUT))[c] =
        make_float4(e.x * inv, e.y * inv, e.z * inv, e.w * inv);
}

extern "C" void kernel_launch(void* const* d_in, const int* in_sizes, int n_in,
                              void* d_out, int out_size) {
    const float* x         = (const float*)d_in[0];
    const int*   edge_src  = (const int*)d_in[1];
    const int*   edge_dst  = (const int*)d_in[2];
    const float* edge_vals = (const float*)d_in[3];
    const float* W1        = (const float*)d_in[4];
    const float* W2        = (const float*)d_in[5];
    const float* W3        = (const float*)d_in[6];
    float* out = (float*)d_out;

    float *h0, *u, *v;
    cudaGetSymbolAddress((void**)&h0, g_h0);
    cudaGetSymbolAddress((void**)&u, g_u);
    cudaGetSymbolAddress((void**)&v, g_v);

    const int G1_SMEM = (DIM_IN * DIM_H + G1_ROWS * DIM_IN) * sizeof(float); // 64KB
    cudaFuncSetAttribute(kernelA,
                         cudaFuncAttributeMaxDynamicSharedMemorySize, G1_SMEM);

    // 1. gemm1 || hist+rank || W23
    kernelA<<<GEMM1_BLOCKS + HIST_BLOCKS + 1, 256, G1_SMEM>>>(x, W1, W2, W3, edge_dst);

    // 2-4. CSR build (atomic-free scatter)
    scan1_kernel<<<SCAN_BLOCKS, 1024>>>();
    scan23_kernel<<<SCAN_BLOCKS, 1024>>>();
    scatter_kernel<<<(N_EDGES / 4 + 255) / 256, 256>>>(edge_src, edge_dst, edge_vals);

    // 5. u = tanh(spmm64(h0)) @ W23  (fused)
    layer2_kernel<<<N_NODES / 16, 256>>>(h0);

    // 6. v = spmm16(u)
    spmm16_csr_kernel<<<(N_NODES * 4 + 255) / 256, 256>>>(u, v);

    // 7. out = softmax(spmm16(v))
    spmm16_softmax_kernel<<<(N_NODES * 4 + 255) / 256, 256>>>(v, out);
}